// round 13
// baseline (speedup 1.0000x reference)
#include <cuda_runtime.h>

// Attention_72447508349519 — algebraic collapse:
//   softmax rows sum to 1 and einsum('bqk,bvd->bqd') contracts k and v
//   independently, so out[b,q,d] = sum_n v[b,n,d] for every q.
//   Pipeline (R10 structure): k1 (stats+weighted colsums) -> k2 (fold) ->
//   k3 (GEMV Wv) -> k4 (GEMV Wo + 64MB broadcast store).
//   R13 cache policy: out is streamed (__stcs) so it never claims L2;
//   x / P / W use DEFAULT policy -> x (64MB) + W (8MB) + P (8MB) fit in the
//   126MB L2 and stay resident ACROSS graph replays, making k1's reads and
//   the GEMV W-loads L2 hits. (R10's __ldcs on x was forcing x back to DRAM
//   every replay — that's why k1 sat at ~3TB/s, latency-bound.)
// Unused inputs: Wq,bq,Wk,bk.

#define BSZ   16
#define CDIM  1024
#define NPOS  1024
#define NGRP  32
#define GROWS 32
#define EPS   1e-5f

__device__ float g_P[BSZ * NGRP * CDIM];
__device__ float g_mean[BSZ * NGRP];
__device__ float g_rstd[BSZ * NGRP];
__device__ float g_s[BSZ * CDIM];
__device__ float g_vsum[BSZ * CDIM];

// ---------------------------------------------------------------------------
// k1: per (b,g) CTA, one pass over the 1024x32 slab of x.
// fj/gq lane mapping: warp = 4 rows x 8 float4 slots -> every LDG.128 covers
// exactly 4 fully-used 128B lines. Block 512, MLP=8 batches, 2 CTAs/SM.
// Default-policy loads: x stays L2-resident across replays.
// ---------------------------------------------------------------------------
#define PPITCH 1028   // bank = (4*fj + gq) mod 32 -> all 32 lanes distinct

__global__ __launch_bounds__(512, 2) void k1_stats(const float* __restrict__ x,
                                                   const float* __restrict__ gamma) {
    const int b = blockIdx.x >> 5;
    const int g = blockIdx.x & 31;
    const int tid = threadIdx.x;

    __shared__ float sg[GROWS];
    __shared__ float spw[8 * PPITCH];
    __shared__ float reds[16], redq[16];

    if (tid < GROWS) sg[tid] = gamma[g * GROWS + tid];
    __syncthreads();

    const int fj = tid & 7;    // float4 slot within the 32-float group row
    const int gq = tid >> 3;   // channel base (c = gq + 64*k), 0..63
    const float w0 = sg[fj * 4 + 0], w1 = sg[fj * 4 + 1];
    const float w2 = sg[fj * 4 + 2], w3 = sg[fj * 4 + 3];

    const float* xb = x + (size_t)b * CDIM * NPOS + g * GROWS;
    float* mypw = spw + fj * PPITCH;

    float tsum = 0.f, tsq = 0.f;
    #pragma unroll
    for (int k0 = 0; k0 < 16; k0 += 8) {
        float4 t[8];
        #pragma unroll
        for (int i = 0; i < 8; i++) {
            const int c = gq + 64 * (k0 + i);
            t[i] = reinterpret_cast<const float4*>(xb + (size_t)c * NPOS)[fj];
        }
        #pragma unroll
        for (int i = 0; i < 8; i++) {
            const int c = gq + 64 * (k0 + i);
            const float4 v = t[i];
            tsum += (v.x + v.y) + (v.z + v.w);
            tsq  += (v.x * v.x + v.y * v.y) + (v.z * v.z + v.w * v.w);
            mypw[c] = w0 * v.x + w1 * v.y + w2 * v.z + w3 * v.w;
        }
    }
    __syncthreads();

    // Fold the 8 fj-partials per channel (conflict-free, stride-1 c).
    float* Pout = g_P + (b * NGRP + g) * CDIM;
    #pragma unroll
    for (int m = 0; m < 2; m++) {
        const int c = tid + 512 * m;
        float acc = spw[c];
        #pragma unroll
        for (int f = 1; f < 8; f++) acc += spw[f * PPITCH + c];
        Pout[c] = acc;
    }

    // Block reduction for mean/rstd.
    #pragma unroll
    for (int o = 16; o; o >>= 1) {
        tsum += __shfl_xor_sync(0xFFFFFFFFu, tsum, o);
        tsq  += __shfl_xor_sync(0xFFFFFFFFu, tsq,  o);
    }
    const int wid = tid >> 5, lane = tid & 31;
    if (lane == 0) { reds[wid] = tsum; redq[wid] = tsq; }
    __syncthreads();
    if (tid == 0) {
        float S = 0.f, Q = 0.f;
        #pragma unroll
        for (int w = 0; w < 16; w++) { S += reds[w]; Q += redq[w]; }
        const float inv = 1.f / (float)(GROWS * CDIM);
        const float m = S * inv;
        const float var = Q * inv - m * m;
        g_mean[b * NGRP + g] = m;
        g_rstd[b * NGRP + g] = rsqrtf(var + EPS);
    }
}

// ---------------------------------------------------------------------------
// k2: s[b,c] = sum_g rstd[b,g]*(P[b,g,c] - mean[b,g]*Gam_g) + sum_n beta[n]
// P just written by k1 -> L2 hits with default policy.
// ---------------------------------------------------------------------------
__global__ __launch_bounds__(1024) void k2_colsum(const float* __restrict__ gamma,
                                                  const float* __restrict__ beta) {
    const int b = blockIdx.x;
    const int tid = threadIdx.x;

    __shared__ float sgam[CDIM];
    __shared__ float sGam[NGRP];
    __shared__ float sm[NGRP], sr[NGRP];
    __shared__ float redb[32];
    __shared__ float sB;

    sgam[tid] = gamma[tid];
    float bb = beta[tid];
    #pragma unroll
    for (int o = 16; o; o >>= 1) bb += __shfl_xor_sync(0xFFFFFFFFu, bb, o);
    const int wid = tid >> 5, lane = tid & 31;
    if (lane == 0) redb[wid] = bb;
    if (tid < NGRP) { sm[tid] = g_mean[b * NGRP + tid]; sr[tid] = g_rstd[b * NGRP + tid]; }
    __syncthreads();

    if (tid < NGRP) {
        float t = 0.f;
        #pragma unroll
        for (int j = 0; j < GROWS; j++) t += sgam[tid * GROWS + j];
        sGam[tid] = t;
    }
    if (tid == 0) {
        float t = 0.f;
        #pragma unroll
        for (int w = 0; w < 32; w++) t += redb[w];
        sB = t;
    }
    __syncthreads();

    float acc = sB;
    const float* Pb = g_P + b * NGRP * CDIM + tid;
    #pragma unroll
    for (int g = 0; g < NGRP; g++)
        acc += sr[g] * (Pb[g * CDIM] - sm[g] * sGam[g]);
    g_s[b * CDIM + tid] = acc;
}

// ---------------------------------------------------------------------------
// k3: vsum[b,d] = s[b,:].Wv[d,:] + 1024*bv[d]
// grid (128 d-tiles, 8 batch-groups) = 1024 CTAs, 256 thr, 8KB smem.
// W default policy -> stays L2-resident across replays.
// ---------------------------------------------------------------------------
__global__ __launch_bounds__(256) void k3_gemv_v(const float* __restrict__ W,
                                                 const float* __restrict__ bias) {
    const int bg = blockIdx.y;           // batches 2*bg, 2*bg+1
    const int tid = threadIdx.x;
    const int wid = tid >> 5, lane = tid & 31;
    const int d = blockIdx.x * 8 + wid;

    __shared__ float ss[2 * CDIM];       // 8 KB

    const float4* wrow = reinterpret_cast<const float4*>(W + (size_t)d * CDIM);
    float4 wreg[8];
    #pragma unroll
    for (int j = 0; j < 8; j++) wreg[j] = wrow[lane + 32 * j];

    {
        const float4* src = reinterpret_cast<const float4*>(g_s + bg * 2 * CDIM);
        float4* dst = reinterpret_cast<float4*>(ss);
        #pragma unroll
        for (int m = 0; m < 2; m++) dst[tid + 256 * m] = src[tid + 256 * m];
    }
    __syncthreads();

    float acc[2] = {0.f, 0.f};
    #pragma unroll
    for (int j = 0; j < 8; j++) {
        const float4 wv = wreg[j];
        #pragma unroll
        for (int q = 0; q < 2; q++) {
            const float4 sv = reinterpret_cast<const float4*>(ss + q * CDIM)[lane + 32 * j];
            acc[q] += wv.x * sv.x + wv.y * sv.y + wv.z * sv.z + wv.w * sv.w;
        }
    }
    #pragma unroll
    for (int q = 0; q < 2; q++)
        #pragma unroll
        for (int o = 16; o; o >>= 1)
            acc[q] += __shfl_xor_sync(0xFFFFFFFFu, acc[q], o);

    if (lane == 0) {
        const float bs = (float)NPOS * bias[d];
        #pragma unroll
        for (int q = 0; q < 2; q++)
            g_vsum[(bg * 2 + q) * CDIM + d] = acc[q] + bs;
    }
}

// ---------------------------------------------------------------------------
// k4: y[b,d] = vsum[b,:].Wo[d,:] + bo[d], fused with the 64MB broadcast
// store out[b,d,:] = y[b,d] via __stcs (out never claims L2 -> x/W stay
// resident; writeback drains in k4's own window). grid (128, 8).
// ---------------------------------------------------------------------------
__global__ __launch_bounds__(256) void k4_gemv_o_bcast(const float* __restrict__ W,
                                                       const float* __restrict__ bias,
                                                       float* __restrict__ out) {
    const int bg = blockIdx.y;           // batches 2*bg, 2*bg+1
    const int tid = threadIdx.x;
    const int wid = tid >> 5, lane = tid & 31;
    const int d = blockIdx.x * 8 + wid;

    __shared__ float ss[2 * CDIM];       // 8 KB

    const float4* wrow = reinterpret_cast<const float4*>(W + (size_t)d * CDIM);
    float4 wreg[8];
    #pragma unroll
    for (int j = 0; j < 8; j++) wreg[j] = wrow[lane + 32 * j];

    {
        const float4* src = reinterpret_cast<const float4*>(g_vsum + bg * 2 * CDIM);
        float4* dst = reinterpret_cast<float4*>(ss);
        #pragma unroll
        for (int m = 0; m < 2; m++) dst[tid + 256 * m] = src[tid + 256 * m];
    }
    __syncthreads();

    float acc[2] = {0.f, 0.f};
    #pragma unroll
    for (int j = 0; j < 8; j++) {
        const float4 wv = wreg[j];
        #pragma unroll
        for (int q = 0; q < 2; q++) {
            const float4 sv = reinterpret_cast<const float4*>(ss + q * CDIM)[lane + 32 * j];
            acc[q] += wv.x * sv.x + wv.y * sv.y + wv.z * sv.z + wv.w * sv.w;
        }
    }
    // Butterfly: every lane ends with the full sum -> whole warp streams stores.
    #pragma unroll
    for (int q = 0; q < 2; q++)
        #pragma unroll
        for (int o = 16; o; o >>= 1)
            acc[q] += __shfl_xor_sync(0xFFFFFFFFu, acc[q], o);

    const float bs = bias[d];
    #pragma unroll
    for (int q = 0; q < 2; q++) {
        const float v = acc[q] + bs;
        const float4 vv = make_float4(v, v, v, v);
        float4* row = reinterpret_cast<float4*>(
            out + ((size_t)((bg * 2 + q) * CDIM + d)) * NPOS);
        #pragma unroll
        for (int t = 0; t < 8; t++) __stcs(&row[lane + 32 * t], vv);
    }
}

extern "C" void kernel_launch(void* const* d_in, const int* in_sizes, int n_in,
                              void* d_out, int out_size) {
    const float* x     = (const float*)d_in[0];
    const float* gamma = (const float*)d_in[1];
    const float* beta  = (const float*)d_in[2];
    // d_in[3..6] = Wq,bq,Wk,bk : provably unused (softmax rows sum to 1).
    const float* Wv    = (const float*)d_in[7];
    const float* bv    = (const float*)d_in[8];
    const float* Wo    = (const float*)d_in[9];
    const float* bo    = (const float*)d_in[10];
    float* out = (float*)d_out;

    k1_stats<<<BSZ * NGRP, 512>>>(x, gamma);
    k2_colsum<<<BSZ, 1024>>>(gamma, beta);
    k3_gemv_v<<<dim3(CDIM / 8, 8), 256>>>(Wv, bv);
    k4_gemv_o_bcast<<<dim3(CDIM / 8, 8), 256>>>(Wo, bo, out);
}

// round 14
// speedup vs baseline: 1.0445x; 1.0445x over previous
#include <cuda_runtime.h>

// Attention_72447508349519 — algebraic collapse:
//   softmax rows sum to 1 and einsum('bqk,bvd->bqd') contracts k and v
//   independently, so out[b,q,d] = sum_n v[b,n,d] for every q.
//   Pipeline (R10 kernels + PDL overlap):
//   k1 (stats+weighted colsums, __ldcs x) -> k2 (fold) -> k3 (GEMV Wv) ->
//   k4 (GEMV Wo + 64MB broadcast store, __stcs).
//   k2/k3/k4 use programmatic dependent launch: each issues its independent
//   prologue (W-row DRAM loads!) BEFORE griddepcontrol.wait, hiding launch
//   gaps and the GEMV cold-W head under the predecessor's execution.
// Unused inputs: Wq,bq,Wk,bk.

#define BSZ   16
#define CDIM  1024
#define NPOS  1024
#define NGRP  32
#define GROWS 32
#define EPS   1e-5f

#define GDC_LAUNCH() asm volatile("griddepcontrol.launch_dependents;" ::: "memory")
#define GDC_WAIT()   asm volatile("griddepcontrol.wait;" ::: "memory")

__device__ float g_P[BSZ * NGRP * CDIM];
__device__ float g_mean[BSZ * NGRP];
__device__ float g_rstd[BSZ * NGRP];
__device__ float g_s[BSZ * CDIM];
__device__ float g_vsum[BSZ * CDIM];

// ---------------------------------------------------------------------------
// k1 (R10-proven): per (b,g) CTA, one pass over the 1024x32 slab of x.
// fj/gq lane mapping (every LDG.128 = 4 fully-used lines), MLP=8, 2 CTAs/SM.
// x loads / P stores streaming (evict-first) — R10's empirically best policy.
// ---------------------------------------------------------------------------
#define PPITCH 1028   // bank = (4*fj + gq) mod 32 -> all 32 lanes distinct

__global__ __launch_bounds__(512, 2) void k1_stats(const float* __restrict__ x,
                                                   const float* __restrict__ gamma) {
    // Let dependents begin their prologues immediately (they still wait for
    // k1 grid completion before consuming g_P/g_mean).
    GDC_LAUNCH();

    const int b = blockIdx.x >> 5;
    const int g = blockIdx.x & 31;
    const int tid = threadIdx.x;

    __shared__ float sg[GROWS];
    __shared__ float spw[8 * PPITCH];
    __shared__ float reds[16], redq[16];

    if (tid < GROWS) sg[tid] = gamma[g * GROWS + tid];
    __syncthreads();

    const int fj = tid & 7;    // float4 slot within the 32-float group row
    const int gq = tid >> 3;   // channel base (c = gq + 64*k), 0..63
    const float w0 = sg[fj * 4 + 0], w1 = sg[fj * 4 + 1];
    const float w2 = sg[fj * 4 + 2], w3 = sg[fj * 4 + 3];

    const float* xb = x + (size_t)b * CDIM * NPOS + g * GROWS;
    float* mypw = spw + fj * PPITCH;

    float tsum = 0.f, tsq = 0.f;
    #pragma unroll
    for (int k0 = 0; k0 < 16; k0 += 8) {
        float4 t[8];
        #pragma unroll
        for (int i = 0; i < 8; i++) {
            const int c = gq + 64 * (k0 + i);
            t[i] = __ldcs(&reinterpret_cast<const float4*>(xb + (size_t)c * NPOS)[fj]);
        }
        #pragma unroll
        for (int i = 0; i < 8; i++) {
            const int c = gq + 64 * (k0 + i);
            const float4 v = t[i];
            tsum += (v.x + v.y) + (v.z + v.w);
            tsq  += (v.x * v.x + v.y * v.y) + (v.z * v.z + v.w * v.w);
            mypw[c] = w0 * v.x + w1 * v.y + w2 * v.z + w3 * v.w;
        }
    }
    __syncthreads();

    // Fold the 8 fj-partials per channel (conflict-free, stride-1 c).
    float* Pout = g_P + (b * NGRP + g) * CDIM;
    #pragma unroll
    for (int m = 0; m < 2; m++) {
        const int c = tid + 512 * m;
        float acc = spw[c];
        #pragma unroll
        for (int f = 1; f < 8; f++) acc += spw[f * PPITCH + c];
        __stcs(&Pout[c], acc);
    }

    // Block reduction for mean/rstd.
    #pragma unroll
    for (int o = 16; o; o >>= 1) {
        tsum += __shfl_xor_sync(0xFFFFFFFFu, tsum, o);
        tsq  += __shfl_xor_sync(0xFFFFFFFFu, tsq,  o);
    }
    const int wid = tid >> 5, lane = tid & 31;
    if (lane == 0) { reds[wid] = tsum; redq[wid] = tsq; }
    __syncthreads();
    if (tid == 0) {
        float S = 0.f, Q = 0.f;
        #pragma unroll
        for (int w = 0; w < 16; w++) { S += reds[w]; Q += redq[w]; }
        const float inv = 1.f / (float)(GROWS * CDIM);
        const float m = S * inv;
        const float var = Q * inv - m * m;
        g_mean[b * NGRP + g] = m;
        g_rstd[b * NGRP + g] = rsqrtf(var + EPS);
    }
}

// ---------------------------------------------------------------------------
// k2: s[b,c] = sum_g rstd[b,g]*(P[b,g,c] - mean[b,g]*Gam_g) + sum_n beta[n]
// PDL: gamma/beta prologue runs pre-wait (independent of k1).
// ---------------------------------------------------------------------------
__global__ __launch_bounds__(1024) void k2_colsum(const float* __restrict__ gamma,
                                                  const float* __restrict__ beta) {
    const int b = blockIdx.x;
    const int tid = threadIdx.x;

    __shared__ float sgam[CDIM];
    __shared__ float sGam[NGRP];
    __shared__ float sm[NGRP], sr[NGRP];
    __shared__ float redb[32];
    __shared__ float sB;

    // Prologue (independent inputs only).
    sgam[tid] = gamma[tid];
    float bb = beta[tid];
    #pragma unroll
    for (int o = 16; o; o >>= 1) bb += __shfl_xor_sync(0xFFFFFFFFu, bb, o);
    const int wid = tid >> 5, lane = tid & 31;
    if (lane == 0) redb[wid] = bb;

    GDC_LAUNCH();        // let k3 start its W prologue
    GDC_WAIT();          // k1's g_P/g_mean/g_rstd now visible

    if (tid < NGRP) { sm[tid] = g_mean[b * NGRP + tid]; sr[tid] = g_rstd[b * NGRP + tid]; }
    __syncthreads();

    if (tid < NGRP) {
        float t = 0.f;
        #pragma unroll
        for (int j = 0; j < GROWS; j++) t += sgam[tid * GROWS + j];
        sGam[tid] = t;
    }
    if (tid == 0) {
        float t = 0.f;
        #pragma unroll
        for (int w = 0; w < 32; w++) t += redb[w];
        sB = t;
    }
    __syncthreads();

    float acc = sB;
    const float* Pb = g_P + b * NGRP * CDIM + tid;
    #pragma unroll
    for (int g = 0; g < NGRP; g++)
        acc += sr[g] * (__ldcs(&Pb[g * CDIM]) - sm[g] * sGam[g]);
    g_s[b * CDIM + tid] = acc;
}

// ---------------------------------------------------------------------------
// k3: vsum[b,d] = s[b,:].Wv[d,:] + 1024*bv[d]
// grid (128 d-tiles, 8 batch-groups) = 1024 CTAs, 256 thr, 8KB smem.
// PDL: the 4MB Wv fetch is issued BEFORE the wait -> overlaps k1/k2.
// ---------------------------------------------------------------------------
__global__ __launch_bounds__(256) void k3_gemv_v(const float* __restrict__ W,
                                                 const float* __restrict__ bias) {
    const int bg = blockIdx.y;           // batches 2*bg, 2*bg+1
    const int tid = threadIdx.x;
    const int wid = tid >> 5, lane = tid & 31;
    const int d = blockIdx.x * 8 + wid;

    __shared__ float ss[2 * CDIM];       // 8 KB

    // Prologue: issue W-row loads (independent of k1/k2 outputs).
    const float4* wrow = reinterpret_cast<const float4*>(W + (size_t)d * CDIM);
    float4 wreg[8];
    #pragma unroll
    for (int j = 0; j < 8; j++) wreg[j] = wrow[lane + 32 * j];
    const float bs0 = bias[d];

    GDC_LAUNCH();        // let k4 start its W prologue
    GDC_WAIT();          // g_s now visible

    {
        const float4* src = reinterpret_cast<const float4*>(g_s + bg * 2 * CDIM);
        float4* dst = reinterpret_cast<float4*>(ss);
        #pragma unroll
        for (int m = 0; m < 2; m++) dst[tid + 256 * m] = src[tid + 256 * m];
    }
    __syncthreads();

    float acc[2] = {0.f, 0.f};
    #pragma unroll
    for (int j = 0; j < 8; j++) {
        const float4 wv = wreg[j];
        #pragma unroll
        for (int q = 0; q < 2; q++) {
            const float4 sv = reinterpret_cast<const float4*>(ss + q * CDIM)[lane + 32 * j];
            acc[q] += wv.x * sv.x + wv.y * sv.y + wv.z * sv.z + wv.w * sv.w;
        }
    }
    #pragma unroll
    for (int q = 0; q < 2; q++)
        #pragma unroll
        for (int o = 16; o; o >>= 1)
            acc[q] += __shfl_xor_sync(0xFFFFFFFFu, acc[q], o);

    if (lane == 0) {
        const float bs = (float)NPOS * bs0;
        #pragma unroll
        for (int q = 0; q < 2; q++)
            g_vsum[(bg * 2 + q) * CDIM + d] = acc[q] + bs;
    }
}

// ---------------------------------------------------------------------------
// k4: y[b,d] = vsum[b,:].Wo[d,:] + bo[d], fused with the 64MB broadcast
// store out[b,d,:] = y[b,d] via __stcs. grid (128, 8) = 1024 CTAs.
// PDL: Wo fetch issued pre-wait -> k4 body starts as pure store drain.
// ---------------------------------------------------------------------------
__global__ __launch_bounds__(256) void k4_gemv_o_bcast(const float* __restrict__ W,
                                                       const float* __restrict__ bias,
                                                       float* __restrict__ out) {
    const int bg = blockIdx.y;           // batches 2*bg, 2*bg+1
    const int tid = threadIdx.x;
    const int wid = tid >> 5, lane = tid & 31;
    const int d = blockIdx.x * 8 + wid;

    __shared__ float ss[2 * CDIM];       // 8 KB

    // Prologue: issue W-row loads (independent of k3's output).
    const float4* wrow = reinterpret_cast<const float4*>(W + (size_t)d * CDIM);
    float4 wreg[8];
    #pragma unroll
    for (int j = 0; j < 8; j++) wreg[j] = wrow[lane + 32 * j];
    const float bs = bias[d];

    GDC_WAIT();          // g_vsum now visible

    {
        const float4* src = reinterpret_cast<const float4*>(g_vsum + bg * 2 * CDIM);
        float4* dst = reinterpret_cast<float4*>(ss);
        #pragma unroll
        for (int m = 0; m < 2; m++) dst[tid + 256 * m] = src[tid + 256 * m];
    }
    __syncthreads();

    float acc[2] = {0.f, 0.f};
    #pragma unroll
    for (int j = 0; j < 8; j++) {
        const float4 wv = wreg[j];
        #pragma unroll
        for (int q = 0; q < 2; q++) {
            const float4 sv = reinterpret_cast<const float4*>(ss + q * CDIM)[lane + 32 * j];
            acc[q] += wv.x * sv.x + wv.y * sv.y + wv.z * sv.z + wv.w * sv.w;
        }
    }
    // Butterfly: every lane ends with the full sum -> whole warp streams stores.
    #pragma unroll
    for (int q = 0; q < 2; q++)
        #pragma unroll
        for (int o = 16; o; o >>= 1)
            acc[q] += __shfl_xor_sync(0xFFFFFFFFu, acc[q], o);

    #pragma unroll
    for (int q = 0; q < 2; q++) {
        const float v = acc[q] + bs;
        const float4 vv = make_float4(v, v, v, v);
        float4* row = reinterpret_cast<float4*>(
            out + ((size_t)((bg * 2 + q) * CDIM + d)) * NPOS);
        #pragma unroll
        for (int t = 0; t < 8; t++) __stcs(&row[lane + 32 * t], vv);
    }
}

// ---------------------------------------------------------------------------
// Launch helpers: PDL attribute on the dependent kernels.
// ---------------------------------------------------------------------------
template <typename F, typename... Args>
static inline void launch_pdl(F f, dim3 grid, dim3 block, Args... args) {
    cudaLaunchConfig_t cfg = {};
    cfg.gridDim = grid;
    cfg.blockDim = block;
    cfg.dynamicSmemBytes = 0;
    cfg.stream = 0;
    cudaLaunchAttribute attr[1];
    attr[0].id = cudaLaunchAttributeProgrammaticStreamSerialization;
    attr[0].val.programmaticStreamSerializationAllowed = 1;
    cfg.attrs = attr;
    cfg.numAttrs = 1;
    cudaLaunchKernelEx(&cfg, f, args...);
}

extern "C" void kernel_launch(void* const* d_in, const int* in_sizes, int n_in,
                              void* d_out, int out_size) {
    const float* x     = (const float*)d_in[0];
    const float* gamma = (const float*)d_in[1];
    const float* beta  = (const float*)d_in[2];
    // d_in[3..6] = Wq,bq,Wk,bk : provably unused (softmax rows sum to 1).
    const float* Wv    = (const float*)d_in[7];
    const float* bv    = (const float*)d_in[8];
    const float* Wo    = (const float*)d_in[9];
    const float* bo    = (const float*)d_in[10];
    float* out = (float*)d_out;

    k1_stats<<<BSZ * NGRP, 512>>>(x, gamma);
    launch_pdl(k2_colsum, dim3(BSZ), dim3(1024), gamma, beta);
    launch_pdl(k3_gemv_v, dim3(CDIM / 8, 8), dim3(256), Wv, bv);
    launch_pdl(k4_gemv_o_bcast, dim3(CDIM / 8, 8), dim3(256), Wo, bo, out);
}